// round 8
// baseline (speedup 1.0000x reference)
#include <cuda_runtime.h>
#include <cuda_fp16.h>
#include <cstdint>

#define D_MODEL 768
#define D_CONV  4
#define D_INNER 1536
#define BATCH   2
#define SEQ     8192
#define MTOT    (BATCH*SEQ)     // 16384

#define K1  D_MODEL             // 768
#define N1  (2*D_INNER)         // 3072
#define K2  D_INNER             // 1536
#define N2  D_MODEL             // 768

#define BM 128
#define BN 256
#define BK 64                   // fp16 per chunk: 128 B/row = SW128 atom
#define STAGES 3
#define NTHREADS 256

#define LCHUNK 512
#define WARM   128

// ---------------- scratch (static device globals; no allocation) -----------
__device__ __half g_a1[(size_t)MTOT * K1];    // fp16(x)        (25 MB)
__device__ __half g_b1[(size_t)N1  * K1];     // fp16(in_w^T)   (4.7 MB)
__device__ __half g_xz[(size_t)MTOT * N1];    // GEMM1 out fp16 (100 MB)
__device__ __half g_a2[(size_t)MTOT * K2];    // fp16(y)        (50 MB)
__device__ __half g_b2[(size_t)N2  * K2];     // fp16(out_w^T)  (2.4 MB)

// ---------------- PTX helpers ----------------------------------------------
__device__ __forceinline__ uint32_t smem_u32(const void* p) {
    uint32_t a;
    asm("{ .reg .u64 t; cvta.to.shared.u64 t, %1; cvt.u32.u64 %0, t; }" : "=r"(a) : "l"(p));
    return a;
}
#define SWZ128(off) ((off) ^ (((off) >> 3) & 0x70))

#define CP_ASYNC16(s, g) \
    asm volatile("cp.async.cg.shared.global [%0], [%1], 16;\n" :: "r"(s), "l"(g) : "memory")
#define CP_COMMIT() asm volatile("cp.async.commit_group;\n" ::: "memory")
#define CP_WAIT(n)  asm volatile("cp.async.wait_group %0;\n" :: "n"(n) : "memory")

#define LDMATRIX_X4(r0, r1, r2, r3, addr) \
    asm volatile("ldmatrix.sync.aligned.m8n8.x4.shared.b16 {%0,%1,%2,%3}, [%4];" \
        : "=r"(r0), "=r"(r1), "=r"(r2), "=r"(r3) : "r"(addr))

#define MMA_F16(d0,d1,d2,d3, a0,a1,a2,a3, b0,b1) \
    asm volatile("mma.sync.aligned.m16n8k16.row.col.f32.f16.f16.f32 " \
        "{%0,%1,%2,%3}, {%4,%5,%6,%7}, {%8,%9}, {%0,%1,%2,%3};" \
        : "+f"(d0), "+f"(d1), "+f"(d2), "+f"(d3) \
        : "r"(a0), "r"(a1), "r"(a2), "r"(a3), "r"(b0), "r"(b1))

// fast sigmoid-based silu: one MUFU (tanh.approx) instead of exp+rcp
__device__ __forceinline__ float fast_silu(float v) {
    float t;
    asm("tanh.approx.f32 %0, %1;" : "=f"(t) : "f"(0.5f * v));
    return v * 0.5f * (t + 1.0f);
}

// SMEM per stage: A 128x64 fp16 (16 KB) + B 256x64 fp16 (32 KB)
#define A_BYTES (BM * 128)
#define B_BYTES (BN * 128)
#define STAGE_BYTES (A_BYTES + B_BYTES)     // 49152
#define SMEM_TOTAL (STAGES * STAGE_BYTES)   // 147456

// ---------------------------------------------------------------------------
// mma.sync fp16 GEMM: C[M,N] (fp32 or fp16) = A[M,K] @ Bt[N,K]^T + bias
// 128x256x64 tile, warp tile 64x64 (2Mx4N warps), 3-stage cp.async, 1 CTA/SM.
// ---------------------------------------------------------------------------
template<typename OutT>
__global__ __launch_bounds__(NTHREADS, 1)
void gemm_f16_mma(const __half* __restrict__ A,
                  const __half* __restrict__ Bt,
                  const float* __restrict__ bias,
                  OutT* __restrict__ C,
                  int M, int N, int K)
{
    extern __shared__ char smem[];
    const uint32_t sbase = smem_u32(smem);
    const int tid  = threadIdx.x;
    const int wid  = tid >> 5;
    const int lane = tid & 31;
    const int warpM = wid & 1;          // 0..1 -> 64-row slice
    const int warpN = wid >> 1;         // 0..3 -> 64-col slice

    const int mBase = blockIdx.y * BM;
    const int nBase = blockIdx.x * BN;

    const __half* Abase = A  + (size_t)mBase * K;
    const __half* Bbase = Bt + (size_t)nBase * K;
    const int nchunks = K / BK;

    const int ldRow  = tid >> 3;        // 0..31
    const int ldPart = tid & 7;         // 0..7
    const uint32_t ldOff = SWZ128((uint32_t)(ldRow * 128 + ldPart * 16));

    auto issue_loads = [&](int chunk, int s) {
        const char* ag = (const char*)(Abase + (size_t)chunk * BK) + (size_t)ldRow * K * 2 + ldPart * 16;
        const char* bg = (const char*)(Bbase + (size_t)chunk * BK) + (size_t)ldRow * K * 2 + ldPart * 16;
        const uint32_t sa = sbase + s * STAGE_BYTES + ldOff;
        const uint32_t sb = sa + A_BYTES;
        const size_t gstep = (size_t)32 * K * 2;      // 32 rows per iter
        #pragma unroll
        for (int i = 0; i < 4; i++)          // A: 128 rows
            CP_ASYNC16(sa + i * (32 * 128), ag + i * gstep);
        #pragma unroll
        for (int i = 0; i < 8; i++)          // B: 256 rows
            CP_ASYNC16(sb + i * (32 * 128), bg + i * gstep);
    };

    const int aRowIn = (lane & 7) + ((lane >> 3) & 1) * 8;    // row within 16
    const int aK8    = (lane >> 4) * 8;                       // 0 or 8
    const int bMat   = lane >> 3;
    const int bNIn   = (bMat >> 1) * 8 + (lane & 7);          // n within 16
    const int bK8    = (bMat & 1) * 8;                        // 0 or 8

    float d[4][8][4];                    // [mt][n8][frag] = 128 regs
    #pragma unroll
    for (int i = 0; i < 4; i++)
        #pragma unroll
        for (int j = 0; j < 8; j++)
            #pragma unroll
            for (int k = 0; k < 4; k++) d[i][j][k] = 0.f;

    issue_loads(0, 0); CP_COMMIT();
    issue_loads(1, 1); CP_COMMIT();

    for (int c = 0; c < nchunks; ++c) {
        CP_WAIT(1);
        __syncthreads();
        if (c + 2 < nchunks) issue_loads(c + 2, (c + 2) % STAGES);
        CP_COMMIT();

        const uint32_t sa = sbase + (c % STAGES) * STAGE_BYTES;
        const uint32_t sb = sa + A_BYTES;

        #pragma unroll
        for (int kk = 0; kk < 4; kk++) {
            uint32_t a[4][4];
            #pragma unroll
            for (int mt = 0; mt < 4; mt++) {
                int row  = warpM * 64 + mt * 16 + aRowIn;
                int kcol = kk * 16 + aK8;
                uint32_t addr = sa + SWZ128((uint32_t)(row * 128 + kcol * 2));
                LDMATRIX_X4(a[mt][0], a[mt][1], a[mt][2], a[mt][3], addr);
            }
            uint32_t b[4][4];
            #pragma unroll
            for (int p = 0; p < 4; p++) {
                int n    = warpN * 64 + p * 16 + bNIn;
                int kcol = kk * 16 + bK8;
                uint32_t addr = sb + SWZ128((uint32_t)(n * 128 + kcol * 2));
                LDMATRIX_X4(b[p][0], b[p][1], b[p][2], b[p][3], addr);
            }
            #pragma unroll
            for (int mt = 0; mt < 4; mt++)
                #pragma unroll
                for (int p = 0; p < 4; p++) {
                    MMA_F16(d[mt][2*p  ][0], d[mt][2*p  ][1], d[mt][2*p  ][2], d[mt][2*p  ][3],
                            a[mt][0], a[mt][1], a[mt][2], a[mt][3], b[p][0], b[p][1]);
                    MMA_F16(d[mt][2*p+1][0], d[mt][2*p+1][1], d[mt][2*p+1][2], d[mt][2*p+1][3],
                            a[mt][0], a[mt][1], a[mt][2], a[mt][3], b[p][2], b[p][3]);
                }
        }
    }

    // epilogue: bias + store (fp32 float2 or fp16 __half2)
    #pragma unroll
    for (int mt = 0; mt < 4; mt++) {
        const int row0 = mBase + warpM * 64 + mt * 16 + (lane >> 2);
        #pragma unroll
        for (int nt = 0; nt < 8; nt++) {
            const int col = nBase + warpN * 64 + nt * 8 + 2 * (lane & 3);
            const float2 bv = *reinterpret_cast<const float2*>(&bias[col]);
            float v00 = d[mt][nt][0] + bv.x, v01 = d[mt][nt][1] + bv.y;
            float v10 = d[mt][nt][2] + bv.x, v11 = d[mt][nt][3] + bv.y;
            if constexpr (sizeof(OutT) == 4) {
                float2 o0 = { v00, v01 }, o1 = { v10, v11 };
                *reinterpret_cast<float2*>((float*)C + (size_t)row0 * N + col)       = o0;
                *reinterpret_cast<float2*>((float*)C + (size_t)(row0 + 8) * N + col) = o1;
            } else {
                *reinterpret_cast<__half2*>((__half*)C + (size_t)row0 * N + col)       = __floats2half2_rn(v00, v01);
                *reinterpret_cast<__half2*>((__half*)C + (size_t)(row0 + 8) * N + col) = __floats2half2_rn(v10, v11);
            }
        }
    }
}

// ---------------------------------------------------------------------------
// fp32 -> fp16 conversion kernels
// ---------------------------------------------------------------------------
__global__ __launch_bounds__(256)
void cvt_x_kernel(const float* __restrict__ x, __half* __restrict__ a1) {
    size_t i = ((size_t)blockIdx.x * blockDim.x + threadIdx.x) * 4;
    if (i >= (size_t)MTOT * K1) return;
    float4 v = *reinterpret_cast<const float4*>(&x[i]);
    __half2* o = reinterpret_cast<__half2*>(&a1[i]);
    o[0] = __floats2half2_rn(v.x, v.y);
    o[1] = __floats2half2_rn(v.z, v.w);
}

// w [K,N] -> bt [N,K] fp16, smem-tiled transpose (coalesced both sides)
__global__ __launch_bounds__(256)
void cvt_wT_kernel(const float* __restrict__ w, __half* __restrict__ bt, int K, int N) {
    __shared__ __half tile[32][33];
    const int tx = threadIdx.x & 31;
    const int ty = threadIdx.x >> 5;
    const int kBase = blockIdx.y * 32;
    const int nBase = blockIdx.x * 32;
    #pragma unroll
    for (int i = 0; i < 32; i += 8) {
        int k = kBase + ty + i, n = nBase + tx;
        tile[ty + i][tx] = __float2half_rn(w[(size_t)k * N + n]);
    }
    __syncthreads();
    #pragma unroll
    for (int i = 0; i < 32; i += 8) {
        int n = nBase + ty + i, k = kBase + tx;
        bt[(size_t)n * K + k] = tile[tx][ty + i];
    }
}

// ---------------------------------------------------------------------------
// Fused conv(4)+silu+EMA scan+gate; fp16 xz in, fp16 a2 out.
// 1 channel/thread. alpha^128 ~ 1.4e-6 -> chunk-independent after warm-up.
// silu via tanh.approx (1 MUFU vs 2).
// ---------------------------------------------------------------------------
__global__ __launch_bounds__(128)
void conv_scan_kernel(const __half* __restrict__ xz,
                      const float* __restrict__ cw,
                      const float* __restrict__ cb,
                      const float* __restrict__ Dp,
                      __half* __restrict__ a2)
{
    const int c  = blockIdx.x * 128 + threadIdx.x;   // channel 0..1535
    const int t0 = blockIdx.y * LCHUNK;
    const int b  = blockIdx.z;
    const int ts = (t0 >= WARM) ? (t0 - WARM) : 0;

    const float4 wv = *reinterpret_cast<const float4*>(&cw[(size_t)c * D_CONV]);
    const float cbias = cb[c];
    const float dpar  = Dp[c];
    const float AL = 0.9f, OMA = 0.1f;

    const __half* base = xz + (size_t)b * SEQ * N1;

    float x0 = 0.f, x1 = 0.f, x2 = 0.f;
    #pragma unroll
    for (int dt = 3; dt >= 1; --dt) {
        int t = ts - dt;
        float v = (t >= 0) ? __half2float(base[(size_t)t * N1 + c]) : 0.f;
        x0 = x1; x1 = x2; x2 = v;
    }

    float h = 0.f;
    const int tend = t0 + LCHUNK;

    #pragma unroll 4
    for (int t = ts; t < tend; ++t) {
        float xt = __half2float(base[(size_t)t * N1 + c]);
        float conv = fmaf(wv.w, xt, fmaf(wv.z, x2, fmaf(wv.y, x1, fmaf(wv.x, x0, cbias))));
        x0 = x1; x1 = x2; x2 = xt;
        float xc = fast_silu(conv);
        h = fmaf(AL, h, OMA * xc);
        if (t >= t0) {
            float zv = __half2float(base[(size_t)t * N1 + D_INNER + c]);
            float y = fmaf(xc, dpar, h) * fast_silu(zv);
            a2[((size_t)b * SEQ + t) * K2 + c] = __float2half_rn(y);
        }
    }
}

// ---------------------------------------------------------------------------
extern "C" void kernel_launch(void* const* d_in, const int* in_sizes, int n_in,
                              void* d_out, int out_size)
{
    const float* x      = (const float*)d_in[0];
    const float* in_w   = (const float*)d_in[1];
    const float* in_b   = (const float*)d_in[2];
    const float* conv_w = (const float*)d_in[3];
    const float* conv_b = (const float*)d_in[4];
    const float* Dp     = (const float*)d_in[9];
    const float* out_w  = (const float*)d_in[10];
    const float* out_b  = (const float*)d_in[11];
    float* out = (float*)d_out;

    __half *a1, *b1, *a2, *b2, *xz;
    cudaGetSymbolAddress((void**)&a1, g_a1);
    cudaGetSymbolAddress((void**)&b1, g_b1);
    cudaGetSymbolAddress((void**)&xz, g_xz);
    cudaGetSymbolAddress((void**)&a2, g_a2);
    cudaGetSymbolAddress((void**)&b2, g_b2);

    cudaFuncSetAttribute(gemm_f16_mma<__half>, cudaFuncAttributeMaxDynamicSharedMemorySize, SMEM_TOTAL);
    cudaFuncSetAttribute(gemm_f16_mma<float>,  cudaFuncAttributeMaxDynamicSharedMemorySize, SMEM_TOTAL);

    // conversions
    {
        size_t n4 = (size_t)MTOT * K1 / 4;
        cvt_x_kernel<<<(unsigned)((n4 + 255) / 256), 256>>>(x, a1);
        dim3 gt1(N1 / 32, K1 / 32);
        cvt_wT_kernel<<<gt1, 256>>>(in_w, b1, K1, N1);
        dim3 gt2(N2 / 32, K2 / 32);
        cvt_wT_kernel<<<gt2, 256>>>(out_w, b2, K2, N2);
    }

    // GEMM1: xz(fp16) = x @ in_w + in_b     [16384 x 3072], K=768
    dim3 g1(N1 / BN, MTOT / BM);
    gemm_f16_mma<__half><<<g1, NTHREADS, SMEM_TOTAL>>>(a1, b1, in_b, xz, MTOT, N1, K1);

    // fused conv/silu/scan/gate -> a2 (fp16)
    dim3 g2(D_INNER / 128, SEQ / LCHUNK, BATCH);
    conv_scan_kernel<<<g2, 128>>>(xz, conv_w, conv_b, Dp, a2);

    // GEMM2: out(fp32) = y @ out_w + out_b  [16384 x 768], K=1536
    dim3 g3(N2 / BN, MTOT / BM);
    gemm_f16_mma<float><<<g3, NTHREADS, SMEM_TOTAL>>>(a2, b2, out_b, out, MTOT, N2, K2);
}

// round 9
// speedup vs baseline: 1.4369x; 1.4369x over previous
#include <cuda_runtime.h>
#include <cuda_fp16.h>
#include <cstdint>

#define D_MODEL 768
#define D_CONV  4
#define D_INNER 1536
#define BATCH   2
#define SEQ     8192
#define MTOT    (BATCH*SEQ)     // 16384

#define K1  D_MODEL             // 768
#define N1  (2*D_INNER)         // 3072
#define K2  D_INNER             // 1536
#define N2  D_MODEL             // 768

#define BM 128
#define BN 128
#define BK 64                   // fp16 per chunk: 128 B/row = SW128 atom
#define STAGES 3
#define NTHREADS 256

#define LCHUNK 256
#define WARM   128

// ---------------- scratch (static device globals; no allocation) -----------
__device__ __half g_a1[(size_t)MTOT * K1];    // fp16(x)        (25 MB)
__device__ __half g_b1[(size_t)N1  * K1];     // fp16(in_w^T)   (4.7 MB)
__device__ __half g_xz[(size_t)MTOT * N1];    // GEMM1 out fp16 (100 MB)
__device__ __half g_a2[(size_t)MTOT * K2];    // fp16(y)        (50 MB)
__device__ __half g_b2[(size_t)N2  * K2];     // fp16(out_w^T)  (2.4 MB)

// ---------------- PTX helpers ----------------------------------------------
__device__ __forceinline__ uint32_t smem_u32(const void* p) {
    uint32_t a;
    asm("{ .reg .u64 t; cvta.to.shared.u64 t, %1; cvt.u32.u64 %0, t; }" : "=r"(a) : "l"(p));
    return a;
}
#define SWZ128(off) ((off) ^ (((off) >> 3) & 0x70))

#define CP_ASYNC16(s, g) \
    asm volatile("cp.async.cg.shared.global [%0], [%1], 16;\n" :: "r"(s), "l"(g) : "memory")
#define CP_COMMIT() asm volatile("cp.async.commit_group;\n" ::: "memory")
#define CP_WAIT(n)  asm volatile("cp.async.wait_group %0;\n" :: "n"(n) : "memory")

#define LDMATRIX_X4(r0, r1, r2, r3, addr) \
    asm volatile("ldmatrix.sync.aligned.m8n8.x4.shared.b16 {%0,%1,%2,%3}, [%4];" \
        : "=r"(r0), "=r"(r1), "=r"(r2), "=r"(r3) : "r"(addr))

#define MMA_F16(d0,d1,d2,d3, a0,a1,a2,a3, b0,b1) \
    asm volatile("mma.sync.aligned.m16n8k16.row.col.f32.f16.f16.f32 " \
        "{%0,%1,%2,%3}, {%4,%5,%6,%7}, {%8,%9}, {%0,%1,%2,%3};" \
        : "+f"(d0), "+f"(d1), "+f"(d2), "+f"(d3) \
        : "r"(a0), "r"(a1), "r"(a2), "r"(a3), "r"(b0), "r"(b1))

// fast silu: one MUFU (tanh.approx) instead of exp+rcp
__device__ __forceinline__ float fast_silu(float v) {
    float t;
    asm("tanh.approx.f32 %0, %1;" : "=f"(t) : "f"(0.5f * v));
    return v * 0.5f * (t + 1.0f);
}

// SMEM per stage: A 128x64 fp16 (16 KB) + B 128x64 fp16 (16 KB)
#define A_BYTES (BM * 128)
#define B_BYTES (BN * 128)
#define STAGE_BYTES (A_BYTES + B_BYTES)     // 32768
#define SMEM_TOTAL (STAGES * STAGE_BYTES)   // 98304

// ---------------------------------------------------------------------------
// mma.sync fp16 GEMM: C[M,N] (fp32 or fp16) = A[M,K] @ Bt[N,K]^T + bias
// 128x128x64 tile, warp tile 32x64 (4Mx2N), 3-stage cp.async, 2 CTA/SM.
// ---------------------------------------------------------------------------
template<typename OutT>
__global__ __launch_bounds__(NTHREADS, 2)
void gemm_f16_mma(const __half* __restrict__ A,
                  const __half* __restrict__ Bt,
                  const float* __restrict__ bias,
                  OutT* __restrict__ C,
                  int M, int N, int K)
{
    extern __shared__ char smem[];
    const uint32_t sbase = smem_u32(smem);
    const int tid  = threadIdx.x;
    const int wid  = tid >> 5;
    const int lane = tid & 31;
    const int warpM = wid & 3;          // 0..3  -> 32-row slice
    const int warpN = wid >> 2;         // 0..1  -> 64-col slice

    const int mBase = blockIdx.y * BM;
    const int nBase = blockIdx.x * BN;

    const __half* Abase = A  + (size_t)mBase * K;
    const __half* Bbase = Bt + (size_t)nBase * K;
    const int nchunks = K / BK;

    const int ldRow  = tid >> 3;        // 0..31
    const int ldPart = tid & 7;         // 0..7
    const uint32_t ldOff = SWZ128((uint32_t)(ldRow * 128 + ldPart * 16));

    auto issue_loads = [&](int chunk, int s) {
        const char* ag = (const char*)(Abase + (size_t)chunk * BK) + (size_t)ldRow * K * 2 + ldPart * 16;
        const char* bg = (const char*)(Bbase + (size_t)chunk * BK) + (size_t)ldRow * K * 2 + ldPart * 16;
        const uint32_t sa = sbase + s * STAGE_BYTES + ldOff;
        const uint32_t sb = sa + A_BYTES;
        const size_t gstep = (size_t)32 * K * 2;      // 32 rows per iter
        #pragma unroll
        for (int i = 0; i < 4; i++)
            CP_ASYNC16(sa + i * (32 * 128), ag + i * gstep);
        #pragma unroll
        for (int i = 0; i < 4; i++)
            CP_ASYNC16(sb + i * (32 * 128), bg + i * gstep);
    };

    const int aRowIn = (lane & 7) + ((lane >> 3) & 1) * 8;    // row within 16
    const int aK8    = (lane >> 4) * 8;                       // 0 or 8
    const int bMat   = lane >> 3;
    const int bNIn   = (bMat >> 1) * 8 + (lane & 7);          // n within 16
    const int bK8    = (bMat & 1) * 8;                        // 0 or 8

    float d[2][8][4];
    #pragma unroll
    for (int i = 0; i < 2; i++)
        #pragma unroll
        for (int j = 0; j < 8; j++)
            #pragma unroll
            for (int k = 0; k < 4; k++) d[i][j][k] = 0.f;

    issue_loads(0, 0); CP_COMMIT();
    issue_loads(1, 1); CP_COMMIT();

    for (int c = 0; c < nchunks; ++c) {
        CP_WAIT(1);
        __syncthreads();
        if (c + 2 < nchunks) issue_loads(c + 2, (c + 2) % STAGES);
        CP_COMMIT();

        const uint32_t sa = sbase + (c % STAGES) * STAGE_BYTES;
        const uint32_t sb = sa + A_BYTES;

        #pragma unroll
        for (int kk = 0; kk < 4; kk++) {
            uint32_t a[2][4];
            #pragma unroll
            for (int mt = 0; mt < 2; mt++) {
                int row  = warpM * 32 + mt * 16 + aRowIn;
                int kcol = kk * 16 + aK8;
                uint32_t addr = sa + SWZ128((uint32_t)(row * 128 + kcol * 2));
                LDMATRIX_X4(a[mt][0], a[mt][1], a[mt][2], a[mt][3], addr);
            }
            uint32_t b[4][4];
            #pragma unroll
            for (int p = 0; p < 4; p++) {
                int n    = warpN * 64 + p * 16 + bNIn;
                int kcol = kk * 16 + bK8;
                uint32_t addr = sb + SWZ128((uint32_t)(n * 128 + kcol * 2));
                LDMATRIX_X4(b[p][0], b[p][1], b[p][2], b[p][3], addr);
            }
            #pragma unroll
            for (int mt = 0; mt < 2; mt++)
                #pragma unroll
                for (int p = 0; p < 4; p++) {
                    MMA_F16(d[mt][2*p  ][0], d[mt][2*p  ][1], d[mt][2*p  ][2], d[mt][2*p  ][3],
                            a[mt][0], a[mt][1], a[mt][2], a[mt][3], b[p][0], b[p][1]);
                    MMA_F16(d[mt][2*p+1][0], d[mt][2*p+1][1], d[mt][2*p+1][2], d[mt][2*p+1][3],
                            a[mt][0], a[mt][1], a[mt][2], a[mt][3], b[p][2], b[p][3]);
                }
        }
    }

    // epilogue: bias + store (fp32 float2 or fp16 __half2)
    #pragma unroll
    for (int mt = 0; mt < 2; mt++) {
        const int row0 = mBase + warpM * 32 + mt * 16 + (lane >> 2);
        #pragma unroll
        for (int nt = 0; nt < 8; nt++) {
            const int col = nBase + warpN * 64 + nt * 8 + 2 * (lane & 3);
            const float2 bv = *reinterpret_cast<const float2*>(&bias[col]);
            float v00 = d[mt][nt][0] + bv.x, v01 = d[mt][nt][1] + bv.y;
            float v10 = d[mt][nt][2] + bv.x, v11 = d[mt][nt][3] + bv.y;
            if constexpr (sizeof(OutT) == 4) {
                float2 o0 = { v00, v01 }, o1 = { v10, v11 };
                *reinterpret_cast<float2*>((float*)C + (size_t)row0 * N + col)       = o0;
                *reinterpret_cast<float2*>((float*)C + (size_t)(row0 + 8) * N + col) = o1;
            } else {
                *reinterpret_cast<__half2*>((__half*)C + (size_t)row0 * N + col)       = __floats2half2_rn(v00, v01);
                *reinterpret_cast<__half2*>((__half*)C + (size_t)(row0 + 8) * N + col) = __floats2half2_rn(v10, v11);
            }
        }
    }
}

// ---------------------------------------------------------------------------
// fp32 -> fp16 conversion kernels
// ---------------------------------------------------------------------------
__global__ __launch_bounds__(256)
void cvt_x_kernel(const float* __restrict__ x, __half* __restrict__ a1) {
    size_t i = ((size_t)blockIdx.x * blockDim.x + threadIdx.x) * 4;
    if (i >= (size_t)MTOT * K1) return;
    float4 v = *reinterpret_cast<const float4*>(&x[i]);
    __half2* o = reinterpret_cast<__half2*>(&a1[i]);
    o[0] = __floats2half2_rn(v.x, v.y);
    o[1] = __floats2half2_rn(v.z, v.w);
}

// w [K,N] -> bt [N,K] fp16, smem-tiled transpose (coalesced both sides)
__global__ __launch_bounds__(256)
void cvt_wT_kernel(const float* __restrict__ w, __half* __restrict__ bt, int K, int N) {
    __shared__ __half tile[32][33];
    const int tx = threadIdx.x & 31;
    const int ty = threadIdx.x >> 5;
    const int kBase = blockIdx.y * 32;
    const int nBase = blockIdx.x * 32;
    #pragma unroll
    for (int i = 0; i < 32; i += 8) {
        int k = kBase + ty + i, n = nBase + tx;
        tile[ty + i][tx] = __float2half_rn(w[(size_t)k * N + n]);
    }
    __syncthreads();
    #pragma unroll
    for (int i = 0; i < 32; i += 8) {
        int n = nBase + ty + i, k = kBase + tx;
        bt[(size_t)n * K + k] = tile[tx][ty + i];
    }
}

// ---------------------------------------------------------------------------
// Fused conv(4)+silu+EMA scan+gate; fp16 xz in, fp16 a2 out.
// 1 channel/thread (768 blocks). alpha^128 ~ 1.4e-6 -> chunk-independent.
// ---------------------------------------------------------------------------
__global__ __launch_bounds__(128)
void conv_scan_kernel(const __half* __restrict__ xz,
                      const float* __restrict__ cw,
                      const float* __restrict__ cb,
                      const float* __restrict__ Dp,
                      __half* __restrict__ a2)
{
    const int c  = blockIdx.x * 128 + threadIdx.x;   // channel 0..1535
    const int t0 = blockIdx.y * LCHUNK;
    const int b  = blockIdx.z;
    const int ts = (t0 >= WARM) ? (t0 - WARM) : 0;

    const float4 wv = *reinterpret_cast<const float4*>(&cw[(size_t)c * D_CONV]);
    const float cbias = cb[c];
    const float dpar  = Dp[c];
    const float AL = 0.9f, OMA = 0.1f;

    const __half* base = xz + (size_t)b * SEQ * N1;

    float x0 = 0.f, x1 = 0.f, x2 = 0.f;
    #pragma unroll
    for (int dt = 3; dt >= 1; --dt) {
        int t = ts - dt;
        float v = (t >= 0) ? __half2float(base[(size_t)t * N1 + c]) : 0.f;
        x0 = x1; x1 = x2; x2 = v;
    }

    float h = 0.f;
    const int tend = t0 + LCHUNK;

    #pragma unroll 8
    for (int t = ts; t < tend; ++t) {
        float xt = __half2float(base[(size_t)t * N1 + c]);
        float conv = fmaf(wv.w, xt, fmaf(wv.z, x2, fmaf(wv.y, x1, fmaf(wv.x, x0, cbias))));
        x0 = x1; x1 = x2; x2 = xt;
        float xc = fast_silu(conv);
        h = fmaf(AL, h, OMA * xc);
        if (t >= t0) {
            float zv = __half2float(base[(size_t)t * N1 + D_INNER + c]);
            float y = fmaf(xc, dpar, h) * fast_silu(zv);
            a2[((size_t)b * SEQ + t) * K2 + c] = __float2half_rn(y);
        }
    }
}

// ---------------------------------------------------------------------------
extern "C" void kernel_launch(void* const* d_in, const int* in_sizes, int n_in,
                              void* d_out, int out_size)
{
    const float* x      = (const float*)d_in[0];
    const float* in_w   = (const float*)d_in[1];
    const float* in_b   = (const float*)d_in[2];
    const float* conv_w = (const float*)d_in[3];
    const float* conv_b = (const float*)d_in[4];
    const float* Dp     = (const float*)d_in[9];
    const float* out_w  = (const float*)d_in[10];
    const float* out_b  = (const float*)d_in[11];
    float* out = (float*)d_out;

    __half *a1, *b1, *a2, *b2, *xz;
    cudaGetSymbolAddress((void**)&a1, g_a1);
    cudaGetSymbolAddress((void**)&b1, g_b1);
    cudaGetSymbolAddress((void**)&xz, g_xz);
    cudaGetSymbolAddress((void**)&a2, g_a2);
    cudaGetSymbolAddress((void**)&b2, g_b2);

    cudaFuncSetAttribute(gemm_f16_mma<__half>, cudaFuncAttributeMaxDynamicSharedMemorySize, SMEM_TOTAL);
    cudaFuncSetAttribute(gemm_f16_mma<float>,  cudaFuncAttributeMaxDynamicSharedMemorySize, SMEM_TOTAL);

    // conversions
    {
        size_t n4 = (size_t)MTOT * K1 / 4;
        cvt_x_kernel<<<(unsigned)((n4 + 255) / 256), 256>>>(x, a1);
        dim3 gt1(N1 / 32, K1 / 32);
        cvt_wT_kernel<<<gt1, 256>>>(in_w, b1, K1, N1);
        dim3 gt2(N2 / 32, K2 / 32);
        cvt_wT_kernel<<<gt2, 256>>>(out_w, b2, K2, N2);
    }

    // GEMM1: xz(fp16) = x @ in_w + in_b     [16384 x 3072], K=768
    dim3 g1(N1 / BN, MTOT / BM);
    gemm_f16_mma<__half><<<g1, NTHREADS, SMEM_TOTAL>>>(a1, b1, in_b, xz, MTOT, N1, K1);

    // fused conv/silu/scan/gate -> a2 (fp16), 1 channel/thread
    dim3 g2(D_INNER / 128, SEQ / LCHUNK, BATCH);
    conv_scan_kernel<<<g2, 128>>>(xz, conv_w, conv_b, Dp, a2);

    // GEMM2: out(fp32) = y @ out_w + out_b  [16384 x 768], K=1536
    dim3 g3(N2 / BN, MTOT / BM);
    gemm_f16_mma<float><<<g3, NTHREADS, SMEM_TOTAL>>>(a2, b2, out_b, out, MTOT, N2, K2);
}

// round 10
// speedup vs baseline: 2.0410x; 1.4204x over previous
#include <cuda_runtime.h>
#include <cuda_fp16.h>
#include <cstdint>

#define D_MODEL 768
#define D_CONV  4
#define D_INNER 1536
#define BATCH   2
#define SEQ     8192
#define MTOT    (BATCH*SEQ)     // 16384

#define K1  D_MODEL             // 768
#define N1  (2*D_INNER)         // 3072
#define K2  D_INNER             // 1536
#define N2  D_MODEL             // 768

#define BM 128
#define BN 128
#define BK 64                   // fp16 per chunk: 128 B/row = SW128 atom
#define STAGES 3
#define NTHREADS 256

#define LCHUNK 256
#define WARM   96               // alpha^96 ~ 4e-5: negligible vs error budget

// ---------------- scratch (static device globals; no allocation) -----------
__device__ __half g_a1[(size_t)MTOT * K1];    // fp16(x)        (25 MB)
__device__ __half g_b1[(size_t)N1  * K1];     // fp16(in_w^T), xz-interleaved rows
__device__ float  g_bias1[N1];                // permuted in_b
__device__ __half g_xz[(size_t)MTOT * N1];    // GEMM1 out fp16, cols [x0,z0,x1,z1,...]
__device__ __half g_a2[(size_t)MTOT * K2];    // fp16(y)        (50 MB)
__device__ __half g_b2[(size_t)N2  * K2];     // fp16(out_w^T)  (2.4 MB)

// ---------------- PTX helpers ----------------------------------------------
__device__ __forceinline__ uint32_t smem_u32(const void* p) {
    uint32_t a;
    asm("{ .reg .u64 t; cvta.to.shared.u64 t, %1; cvt.u32.u64 %0, t; }" : "=r"(a) : "l"(p));
    return a;
}
#define SWZ128(off) ((off) ^ (((off) >> 3) & 0x70))

#define CP_ASYNC16(s, g) \
    asm volatile("cp.async.cg.shared.global [%0], [%1], 16;\n" :: "r"(s), "l"(g) : "memory")
#define CP_COMMIT() asm volatile("cp.async.commit_group;\n" ::: "memory")
#define CP_WAIT(n)  asm volatile("cp.async.wait_group %0;\n" :: "n"(n) : "memory")

#define LDMATRIX_X4(r0, r1, r2, r3, addr) \
    asm volatile("ldmatrix.sync.aligned.m8n8.x4.shared.b16 {%0,%1,%2,%3}, [%4];" \
        : "=r"(r0), "=r"(r1), "=r"(r2), "=r"(r3) : "r"(addr))

#define MMA_F16(d0,d1,d2,d3, a0,a1,a2,a3, b0,b1) \
    asm volatile("mma.sync.aligned.m16n8k16.row.col.f32.f16.f16.f32 " \
        "{%0,%1,%2,%3}, {%4,%5,%6,%7}, {%8,%9}, {%0,%1,%2,%3};" \
        : "+f"(d0), "+f"(d1), "+f"(d2), "+f"(d3) \
        : "r"(a0), "r"(a1), "r"(a2), "r"(a3), "r"(b0), "r"(b1))

// fast silu: one MUFU (tanh.approx) instead of exp+rcp
__device__ __forceinline__ float fast_silu(float v) {
    float t;
    asm("tanh.approx.f32 %0, %1;" : "=f"(t) : "f"(0.5f * v));
    return v * 0.5f * (t + 1.0f);
}

// SMEM per stage: A 128x64 fp16 (16 KB) + B 128x64 fp16 (16 KB)
#define A_BYTES (BM * 128)
#define B_BYTES (BN * 128)
#define STAGE_BYTES (A_BYTES + B_BYTES)     // 32768
#define SMEM_TOTAL (STAGES * STAGE_BYTES)   // 98304

// ---------------------------------------------------------------------------
// mma.sync fp16 GEMM: C[M,N] (fp32 or fp16) = A[M,K] @ Bt[N,K]^T + bias
// 128x128x64 tile, warp tile 32x64 (4Mx2N), 3-stage cp.async, 2 CTA/SM.
// ---------------------------------------------------------------------------
template<typename OutT>
__global__ __launch_bounds__(NTHREADS, 2)
void gemm_f16_mma(const __half* __restrict__ A,
                  const __half* __restrict__ Bt,
                  const float* __restrict__ bias,
                  OutT* __restrict__ C,
                  int M, int N, int K)
{
    extern __shared__ char smem[];
    const uint32_t sbase = smem_u32(smem);
    const int tid  = threadIdx.x;
    const int wid  = tid >> 5;
    const int lane = tid & 31;
    const int warpM = wid & 3;          // 0..3  -> 32-row slice
    const int warpN = wid >> 2;         // 0..1  -> 64-col slice

    const int mBase = blockIdx.y * BM;
    const int nBase = blockIdx.x * BN;

    const __half* Abase = A  + (size_t)mBase * K;
    const __half* Bbase = Bt + (size_t)nBase * K;
    const int nchunks = K / BK;

    const int ldRow  = tid >> 3;        // 0..31
    const int ldPart = tid & 7;         // 0..7
    const uint32_t ldOff = SWZ128((uint32_t)(ldRow * 128 + ldPart * 16));

    auto issue_loads = [&](int chunk, int s) {
        const char* ag = (const char*)(Abase + (size_t)chunk * BK) + (size_t)ldRow * K * 2 + ldPart * 16;
        const char* bg = (const char*)(Bbase + (size_t)chunk * BK) + (size_t)ldRow * K * 2 + ldPart * 16;
        const uint32_t sa = sbase + s * STAGE_BYTES + ldOff;
        const uint32_t sb = sa + A_BYTES;
        const size_t gstep = (size_t)32 * K * 2;      // 32 rows per iter
        #pragma unroll
        for (int i = 0; i < 4; i++)
            CP_ASYNC16(sa + i * (32 * 128), ag + i * gstep);
        #pragma unroll
        for (int i = 0; i < 4; i++)
            CP_ASYNC16(sb + i * (32 * 128), bg + i * gstep);
    };

    const int aRowIn = (lane & 7) + ((lane >> 3) & 1) * 8;    // row within 16
    const int aK8    = (lane >> 4) * 8;                       // 0 or 8
    const int bMat   = lane >> 3;
    const int bNIn   = (bMat >> 1) * 8 + (lane & 7);          // n within 16
    const int bK8    = (bMat & 1) * 8;                        // 0 or 8

    float d[2][8][4];
    #pragma unroll
    for (int i = 0; i < 2; i++)
        #pragma unroll
        for (int j = 0; j < 8; j++)
            #pragma unroll
            for (int k = 0; k < 4; k++) d[i][j][k] = 0.f;

    issue_loads(0, 0); CP_COMMIT();
    issue_loads(1, 1); CP_COMMIT();

    for (int c = 0; c < nchunks; ++c) {
        CP_WAIT(1);
        __syncthreads();
        if (c + 2 < nchunks) issue_loads(c + 2, (c + 2) % STAGES);
        CP_COMMIT();

        const uint32_t sa = sbase + (c % STAGES) * STAGE_BYTES;
        const uint32_t sb = sa + A_BYTES;

        #pragma unroll
        for (int kk = 0; kk < 4; kk++) {
            uint32_t a[2][4];
            #pragma unroll
            for (int mt = 0; mt < 2; mt++) {
                int row  = warpM * 32 + mt * 16 + aRowIn;
                int kcol = kk * 16 + aK8;
                uint32_t addr = sa + SWZ128((uint32_t)(row * 128 + kcol * 2));
                LDMATRIX_X4(a[mt][0], a[mt][1], a[mt][2], a[mt][3], addr);
            }
            uint32_t b[4][4];
            #pragma unroll
            for (int p = 0; p < 4; p++) {
                int n    = warpN * 64 + p * 16 + bNIn;
                int kcol = kk * 16 + bK8;
                uint32_t addr = sb + SWZ128((uint32_t)(n * 128 + kcol * 2));
                LDMATRIX_X4(b[p][0], b[p][1], b[p][2], b[p][3], addr);
            }
            #pragma unroll
            for (int mt = 0; mt < 2; mt++)
                #pragma unroll
                for (int p = 0; p < 4; p++) {
                    MMA_F16(d[mt][2*p  ][0], d[mt][2*p  ][1], d[mt][2*p  ][2], d[mt][2*p  ][3],
                            a[mt][0], a[mt][1], a[mt][2], a[mt][3], b[p][0], b[p][1]);
                    MMA_F16(d[mt][2*p+1][0], d[mt][2*p+1][1], d[mt][2*p+1][2], d[mt][2*p+1][3],
                            a[mt][0], a[mt][1], a[mt][2], a[mt][3], b[p][2], b[p][3]);
                }
        }
    }

    // epilogue: bias + store (fp32 float2 or fp16 __half2)
    #pragma unroll
    for (int mt = 0; mt < 2; mt++) {
        const int row0 = mBase + warpM * 32 + mt * 16 + (lane >> 2);
        #pragma unroll
        for (int nt = 0; nt < 8; nt++) {
            const int col = nBase + warpN * 64 + nt * 8 + 2 * (lane & 3);
            const float2 bv = *reinterpret_cast<const float2*>(&bias[col]);
            float v00 = d[mt][nt][0] + bv.x, v01 = d[mt][nt][1] + bv.y;
            float v10 = d[mt][nt][2] + bv.x, v11 = d[mt][nt][3] + bv.y;
            if constexpr (sizeof(OutT) == 4) {
                float2 o0 = { v00, v01 }, o1 = { v10, v11 };
                *reinterpret_cast<float2*>((float*)C + (size_t)row0 * N + col)       = o0;
                *reinterpret_cast<float2*>((float*)C + (size_t)(row0 + 8) * N + col) = o1;
            } else {
                *reinterpret_cast<__half2*>((__half*)C + (size_t)row0 * N + col)       = __floats2half2_rn(v00, v01);
                *reinterpret_cast<__half2*>((__half*)C + (size_t)(row0 + 8) * N + col) = __floats2half2_rn(v10, v11);
            }
        }
    }
}

// ---------------------------------------------------------------------------
// fp32 -> fp16 conversion kernels
// ---------------------------------------------------------------------------
__global__ __launch_bounds__(256)
void cvt_x_kernel(const float* __restrict__ x, __half* __restrict__ a1) {
    size_t i = ((size_t)blockIdx.x * blockDim.x + threadIdx.x) * 4;
    if (i >= (size_t)MTOT * K1) return;
    float4 v = *reinterpret_cast<const float4*>(&x[i]);
    __half2* o = reinterpret_cast<__half2*>(&a1[i]);
    o[0] = __floats2half2_rn(v.x, v.y);
    o[1] = __floats2half2_rn(v.z, v.w);
}

// w [K,N] -> bt [perm(N),K] fp16, smem-tiled transpose (coalesced both sides).
// PERM != 0: interleave x/z halves: n<NH -> 2n ; n>=NH -> 2(n-NH)+1.
template<int PERM, int NH>
__global__ __launch_bounds__(256)
void cvt_wT_kernel(const float* __restrict__ w, __half* __restrict__ bt, int K, int N) {
    __shared__ __half tile[32][33];
    const int tx = threadIdx.x & 31;
    const int ty = threadIdx.x >> 5;
    const int kBase = blockIdx.y * 32;
    const int nBase = blockIdx.x * 32;
    #pragma unroll
    for (int i = 0; i < 32; i += 8) {
        int k = kBase + ty + i, n = nBase + tx;
        tile[ty + i][tx] = __float2half_rn(w[(size_t)k * N + n]);
    }
    __syncthreads();
    #pragma unroll
    for (int i = 0; i < 32; i += 8) {
        int n = nBase + ty + i, k = kBase + tx;
        int np = PERM ? ((n < NH) ? 2 * n : 2 * (n - NH) + 1) : n;
        bt[(size_t)np * K + k] = tile[tx][ty + i];
    }
}

// permute GEMM1 bias into interleaved order
__global__ __launch_bounds__(256)
void perm_bias_kernel(const float* __restrict__ b, float* __restrict__ bp) {
    int n = blockIdx.x * 256 + threadIdx.x;
    if (n >= N1) return;
    int np = (n < D_INNER) ? 2 * n : 2 * (n - D_INNER) + 1;
    bp[np] = b[n];
}

// ---------------------------------------------------------------------------
// Fused conv(4)+silu+EMA scan+gate; interleaved fp16 xz in (x_c@2c, z_c@2c+1),
// fp16 a2 out. One __half2 load per iteration, fully coalesced.
// ---------------------------------------------------------------------------
__global__ __launch_bounds__(128)
void conv_scan_kernel(const __half* __restrict__ xz,
                      const float* __restrict__ cw,
                      const float* __restrict__ cb,
                      const float* __restrict__ Dp,
                      __half* __restrict__ a2)
{
    const int c  = blockIdx.x * 128 + threadIdx.x;   // channel 0..1535
    const int t0 = blockIdx.y * LCHUNK;
    const int b  = blockIdx.z;
    const int ts = (t0 >= WARM) ? (t0 - WARM) : 0;

    const float4 wv = *reinterpret_cast<const float4*>(&cw[(size_t)c * D_CONV]);
    const float cbias = cb[c];
    const float dpar  = Dp[c];
    const float AL = 0.9f, OMA = 0.1f;

    const __half* base = xz + (size_t)b * SEQ * N1 + 2 * c;   // points at (x_c, z_c) pair

    float x0 = 0.f, x1 = 0.f, x2 = 0.f;
    #pragma unroll
    for (int dt = 3; dt >= 1; --dt) {
        int t = ts - dt;
        float v = 0.f;
        if (t >= 0) {
            __half2 p = *reinterpret_cast<const __half2*>(&base[(size_t)t * N1]);
            v = __low2float(p);
        }
        x0 = x1; x1 = x2; x2 = v;
    }

    float h = 0.f;
    const int tend = t0 + LCHUNK;

    #pragma unroll 8
    for (int t = ts; t < tend; ++t) {
        __half2 p = *reinterpret_cast<const __half2*>(&base[(size_t)t * N1]);
        float xt = __low2float(p);
        float zv = __high2float(p);
        float conv = fmaf(wv.w, xt, fmaf(wv.z, x2, fmaf(wv.y, x1, fmaf(wv.x, x0, cbias))));
        x0 = x1; x1 = x2; x2 = xt;
        float xc = fast_silu(conv);
        h = fmaf(AL, h, OMA * xc);
        if (t >= t0) {
            float y = fmaf(xc, dpar, h) * fast_silu(zv);
            a2[((size_t)b * SEQ + t) * K2 + c] = __float2half_rn(y);
        }
    }
}

// ---------------------------------------------------------------------------
extern "C" void kernel_launch(void* const* d_in, const int* in_sizes, int n_in,
                              void* d_out, int out_size)
{
    const float* x      = (const float*)d_in[0];
    const float* in_w   = (const float*)d_in[1];
    const float* in_b   = (const float*)d_in[2];
    const float* conv_w = (const float*)d_in[3];
    const float* conv_b = (const float*)d_in[4];
    const float* Dp     = (const float*)d_in[9];
    const float* out_w  = (const float*)d_in[10];
    const float* out_b  = (const float*)d_in[11];
    float* out = (float*)d_out;

    __half *a1, *b1, *a2, *b2, *xz; float* bias1;
    cudaGetSymbolAddress((void**)&a1, g_a1);
    cudaGetSymbolAddress((void**)&b1, g_b1);
    cudaGetSymbolAddress((void**)&bias1, g_bias1);
    cudaGetSymbolAddress((void**)&xz, g_xz);
    cudaGetSymbolAddress((void**)&a2, g_a2);
    cudaGetSymbolAddress((void**)&b2, g_b2);

    cudaFuncSetAttribute(gemm_f16_mma<__half>, cudaFuncAttributeMaxDynamicSharedMemorySize, SMEM_TOTAL);
    cudaFuncSetAttribute(gemm_f16_mma<float>,  cudaFuncAttributeMaxDynamicSharedMemorySize, SMEM_TOTAL);

    // conversions
    {
        size_t n4 = (size_t)MTOT * K1 / 4;
        cvt_x_kernel<<<(unsigned)((n4 + 255) / 256), 256>>>(x, a1);
        dim3 gt1(N1 / 32, K1 / 32);
        cvt_wT_kernel<1, D_INNER><<<gt1, 256>>>(in_w, b1, K1, N1);   // interleaved rows
        dim3 gt2(N2 / 32, K2 / 32);
        cvt_wT_kernel<0, 0><<<gt2, 256>>>(out_w, b2, K2, N2);
        perm_bias_kernel<<<N1 / 256, 256>>>(in_b, bias1);
    }

    // GEMM1: xz(fp16, interleaved cols) = x @ in_w_perm + in_b_perm   [16384 x 3072]
    dim3 g1(N1 / BN, MTOT / BM);
    gemm_f16_mma<__half><<<g1, NTHREADS, SMEM_TOTAL>>>(a1, b1, bias1, xz, MTOT, N1, K1);

    // fused conv/silu/scan/gate -> a2 (fp16), 1 channel/thread, half2 loads
    dim3 g2(D_INNER / 128, SEQ / LCHUNK, BATCH);
    conv_scan_kernel<<<g2, 128>>>(xz, conv_w, conv_b, Dp, a2);

    // GEMM2: out(fp32) = y @ out_w + out_b  [16384 x 768], K=1536
    dim3 g3(N2 / BN, MTOT / BM);
    gemm_f16_mma<float><<<g3, NTHREADS, SMEM_TOTAL>>>(a2, b2, out_b, out, MTOT, N2, K2);
}